// round 17
// baseline (speedup 1.0000x reference)
#include <cuda_runtime.h>
#include <cuda_bf16.h>
#include <math.h>

// Problem constants (fixed by the dataset)
#define BMAX 1024
#define EMAX 32768

// Setup block layout inside the fused kernel
#define NB_SCAN   1                 // block 0
#define NB_M2     16                // blocks 1..16   (4096 elems / 256)
#define NB_VSELF  64                // blocks 17..80  (16 users each)
#define NB_ZERO   8                 // blocks 81..88
#define NSETUP    (NB_SCAN + NB_M2 + NB_VSELF + NB_ZERO)   // 89

// Scratch (static device globals — no allocation allowed)
__device__ long long g_offsets[BMAX + 1];
__device__ int       g_edge_user[EMAX];
__device__ float     g_M2t[64 * 64];      // [j][d]
__device__ float     g_vself[BMAX * 64];
__device__ int       g_done;              // producers finished (self-resetting)
__device__ int       g_fin;               // blocks finished   (self-resetting)

struct MainSmem {
    float  M2sh[64 * 64];    // 16 KB
    float2 fxp[4][64];
    float  vsh[8][64];
    float  exsh[8][64];
    int    lst[8][64];
};
struct ScanSmem {
    long long ssum[256];
};
struct VsSmem {
    float Wsh[64][65];       // Wf-half, then reused for Wb (stride-65, conflict-free)
    float Psh[16][65];
    float sx[16][64];
};
union KSmem {
    MainSmem m;
    ScanSmem sc;
    VsSmem   vs;
};

__global__ __launch_bounds__(256)
void fused_kernel(const void* __restrict__ counts_raw, int B, int E,
                  const float* __restrict__ Wf, const float* __restrict__ Wb,
                  const float* __restrict__ self_x,
                  const float* __restrict__ common_x,
                  const float* __restrict__ common_time,
                  const int*   __restrict__ common_src_mask,
                  const float* __restrict__ friend_x,
                  float* __restrict__ out, int max_n, long long out_elems) {
    __shared__ KSmem sm;
    int b = blockIdx.x;
    int t = threadIdx.x;

    if (b < NSETUP) {
        // =================== PRODUCERS ===================
        if (b == 0) {
            // ---- scan: 4 counts per thread, dtype-robust ----
            __shared__ int use64;
            long long* ssum = sm.sc.ssum;
            const long long* c64 = (const long long*)counts_raw;
            const int*       c32 = (const int*)counts_raw;

            long long s64 = 0;
#pragma unroll
            for (int k = 0; k < 4; k++) {
                int u = t * 4 + k;
                s64 += (u < B) ? c64[u] : 0;
            }
            ssum[t] = s64;
            __syncthreads();
            for (int o = 128; o > 0; o >>= 1) {
                if (t < o) ssum[t] += ssum[t + o];
                __syncthreads();
            }
            if (t == 0) use64 = (ssum[0] == (long long)E) ? 1 : 0;
            __syncthreads();
            int u64 = use64;
            __syncthreads();

            long long c[4];
            long long tot = 0;
#pragma unroll
            for (int k = 0; k < 4; k++) {
                int u = t * 4 + k;
                long long v = 0;
                if (u < B) v = u64 ? c64[u] : (long long)c32[u];
                if (v < 0) v = 0;
                if (v > (long long)EMAX) v = EMAX;
                c[k] = v;
                tot += v;
            }
            ssum[t] = tot;
            __syncthreads();
            for (int o = 1; o < 256; o <<= 1) {
                long long add = (t >= o) ? ssum[t - o] : 0;
                __syncthreads();
                ssum[t] += add;
                __syncthreads();
            }
            long long run = ssum[t] - tot;   // exclusive base for this thread
            if (t == 0) g_offsets[0] = 0;
#pragma unroll
            for (int k = 0; k < 4; k++) {
                int u = t * 4 + k;
                if (u < B) {
                    g_offsets[u + 1] = run + c[k];
                    for (long long i = 0; i < c[k]; i++) {
                        long long idx = run + i;
                        if (idx >= 0 && idx < (long long)EMAX) g_edge_user[idx] = u;
                    }
                    run += c[k];
                }
            }
        } else if (b <= NB_M2) {
            // ---- M2t: one element per thread ----
            int idx = (b - 1) * 256 + t;       // 0..4095
            int d = idx & 63;
            int j = idx >> 6;
            float acc = 0.f;
#pragma unroll 8
            for (int f = 0; f < 64; f++)
                acc = fmaf(Wb[f * 64 + d], Wf[f * 128 + 64 + j], acc);
            g_M2t[j * 64 + d] = acc;
        } else if (b <= NB_M2 + NB_VSELF) {
            // ---- vself: 16 users/block, factorized ----
            VsSmem& S = sm.vs;
            int ub0 = (b - NB_M2 - 1) * 16;
            for (int i = t; i < 4096; i += 256) {
                int f = i >> 6, j = i & 63;
                S.Wsh[f][j] = Wf[f * 128 + j];        // Wf[:, :64]
            }
            for (int i = t; i < 1024; i += 256) {
                int sub = i >> 6, l = i & 63;
                int u = ub0 + sub;
                S.sx[sub][l] = (u < B) ? self_x[u * 64 + l] : 0.f;
            }
            __syncthreads();
            // step 1: P[sub][f] = Wf[f,:64] . sx[sub]
#pragma unroll
            for (int rep = 0; rep < 4; rep++) {
                int item = rep * 256 + t;
                int sub = item >> 6, l = item & 63;
                float acc = 0.f;
#pragma unroll 16
                for (int j = 0; j < 64; j++)
                    acc = fmaf(S.Wsh[l][j], S.sx[sub][j], acc);
                S.Psh[sub][l] = acc;
            }
            __syncthreads();
            // re-stage Wb into Wsh ([f][d] at stride 65)
            for (int i = t; i < 4096; i += 256) {
                int f = i >> 6, d = i & 63;
                S.Wsh[f][d] = Wb[i];
            }
            __syncthreads();
            // step 2: vself[u][d] = sum_f Wb[f][d] * P[sub][f]
#pragma unroll
            for (int rep = 0; rep < 4; rep++) {
                int item = rep * 256 + t;
                int sub = item >> 6, d = item & 63;
                int u = ub0 + sub;
                float acc = 0.f;
#pragma unroll 16
                for (int f = 0; f < 64; f++)
                    acc = fmaf(S.Wsh[f][d], S.Psh[sub][f], acc);
                if (u < B) g_vself[u * 64 + d] = acc;
            }
        } else {
            // ---- zero the output (padding must be 0) ----
            long long base = (long long)(b - NB_M2 - NB_VSELF - 1) * 256 + t;
            for (long long i = base; i < out_elems; i += (long long)NB_ZERO * 256)
                out[i] = 0.f;
        }
        // signal
        __syncthreads();
        __threadfence();
        if (t == 0) atomicAdd(&g_done, 1);
    } else {
        // =================== WORKERS (main) ===================
        if (t == 0) {
            while (*(volatile int*)&g_done < NSETUP) __nanosleep(128);
        }
        __syncthreads();
        __threadfence();

        MainSmem& M = sm.m;
        int w = t >> 5, lane = t & 31;
        int blk = b - NSETUP;
        int e = blk * 8 + w;

        // stage M2 (block-coop)
        {
            const float4* src = (const float4*)g_M2t;
            float4* dst = (float4*)M.M2sh;
            for (int i = t; i < 1024; i += 256) dst[i] = src[i];
        }
        // stage interleaved fx pairs
        {
            int qq = t >> 6, jj = t & 63;
            int ep = blk * 8 + 2 * qq;
            M.fxp[qq][jj] = make_float2(friend_x[(size_t)ep * 64 + jj],
                                        friend_x[(size_t)(ep + 1) * 64 + jj]);
        }

        // per-warp masks / temporal / compaction
        const int*   mrow = common_src_mask + (size_t)e * 64;
        const float* trow = common_time + (size_t)e * 64;
        int mk0 = mrow[lane];
        int mk1 = mrow[lane + 32];
        M.exsh[w][lane]      = __expf(fmaf(trow[lane],      -1e-6f, 1.0f));
        M.exsh[w][lane + 32] = __expf(fmaf(trow[lane + 32], -1e-6f, 1.0f));
        unsigned bm0 = __ballot_sync(0xffffffffu, mk0 != 0);
        unsigned bm1 = __ballot_sync(0xffffffffu, mk1 != 0);
        int n0 = __popc(bm0);
        if (mk0) M.lst[w][__popc(bm0 & ((1u << lane) - 1u))] = lane;
        if (mk1) M.lst[w][n0 + __popc(bm1 & ((1u << lane) - 1u))] = lane + 32;
        int n_act = n0 + __popc(bm1);
        __syncthreads();

        // Phase A: v for edge pair; thread owns one d of edges 2q,2q+1
        {
            int d = t & 63;
            int q = t >> 6;
            int eA = blk * 8 + 2 * q;
            int uA = g_edge_user[eA], uB = g_edge_user[eA + 1];
            float a0 = g_vself[(size_t)uA * 64 + d];
            float a1 = g_vself[(size_t)uB * 64 + d];
#pragma unroll 8
            for (int j = 0; j < 64; j++) {
                float m = M.M2sh[j * 64 + d];
                float2 f = M.fxp[q][j];
                a0 = fmaf(m, f.x, a0);
                a1 = fmaf(m, f.y, a1);
            }
            M.vsh[2 * q][d]     = a0;
            M.vsh[2 * q + 1][d] = a1;
        }
        __syncthreads();

        // Phase B: quad-streaming over compacted rows
        int h8 = lane & 7, r8 = lane >> 3;
        float4 v4a = *(const float4*)(&M.vsh[w][h8 * 4]);
        float4 v4b = *(const float4*)(&M.vsh[w][(h8 + 8) * 4]);
        const float* base = common_x + (size_t)e * 4096;

        float wacc = 0.f;
        int nq = (n_act + 3) >> 2;
#pragma unroll 4
        for (int g2 = 0; g2 < nq; g2++) {
            int i = g2 * 4 + r8;
            bool valid = i < n_act;
            int r = M.lst[w][valid ? i : 0];
            const float4* rowp = (const float4*)(base + r * 64);
            float4 x1 = rowp[h8];
            float4 x2 = rowp[h8 + 8];
            float p = fmaf(x1.x, v4a.x, fmaf(x1.y, v4a.y,
                      fmaf(x1.z, v4a.z, fmaf(x1.w, v4a.w,
                      fmaf(x2.x, v4b.x, fmaf(x2.y, v4b.y,
                      fmaf(x2.z, v4b.z, x2.w * v4b.w)))))));
            p += __shfl_xor_sync(0xffffffffu, p, 4);
            p += __shfl_xor_sync(0xffffffffu, p, 2);
            p += __shfl_xor_sync(0xffffffffu, p, 1);
            if (valid && h8 == 0) {
                float sp = fmaxf(p, 0.f) + __logf(1.0f + __expf(-fabsf(p)));
                wacc = fmaf(sp, M.exsh[w][r], wacc);
            }
        }
        wacc += __shfl_xor_sync(0xffffffffu, wacc, 8);
        wacc += __shfl_xor_sync(0xffffffffu, wacc, 16);
        if (lane == 0) {
            int u = g_edge_user[e];
            long long oi = (long long)u * max_n + (long long)(e - g_offsets[u]);
            if (oi >= 0 && oi < out_elems)
                out[oi] = wacc;
        }
    }

    // ---- self-resetting finish counter (graph-replay determinism) ----
    __syncthreads();
    if (t == 0) {
        __threadfence();
        int old = atomicAdd(&g_fin, 1);
        if (old == (int)gridDim.x - 1) {
            g_fin = 0;
            g_done = 0;
        }
    }
}

// ---------------------------------------------------------------------------
extern "C" void kernel_launch(void* const* d_in, const int* in_sizes, int n_in,
                              void* d_out, int out_size) {
    const float* self_x      = (const float*)d_in[0];
    const float* common_x    = (const float*)d_in[1];
    const float* common_time = (const float*)d_in[2];
    const int*   src_mask    = (const int*)d_in[3];
    const float* friend_x    = (const float*)d_in[4];
    const void*  counts      = (const void*)d_in[5];
    const float* W_friend    = (const float*)d_in[6];
    const float* W_beta      = (const float*)d_in[7];
    float*       out         = (float*)d_out;

    int B = in_sizes[5];
    int E = in_sizes[4] / 64;
    int max_n = out_size / B;

    int grid = NSETUP + E / 8;
    fused_kernel<<<grid, 256>>>(counts, B, E, W_friend, W_beta, self_x,
                                common_x, common_time, src_mask, friend_x,
                                out, max_n, (long long)out_size);
}